// round 16
// baseline (speedup 1.0000x reference)
#include <cuda_runtime.h>

// Fused sum-over-seq + concat:  out[b,i,d] = sum_l x_i[b,l,d]
// 8 inputs x_i : [512, L_i, 128] fp32, L_i = 64*(i+1); out : [512, 8, 128] fp32.
//
// R16 = R14 with the pipeline off-by-one fixed.
//   Double-buffered 8-row batches: batch k+1's LDG.128s issue before batch k's
//   FADD chain -> the warp always has >=8 loads in flight (R13 oscillated
//   16 -> 0 per 16-row batch).
//   Batch audit (N = L/8 batches, N even): prologue loads batch 0; the loop
//   runs N/2 - 1 double-iterations consuming batches 1..N-2; the epilogue
//   loads batch N-1 and drains both buffers. Exactly N batches, no OOB.
//   Scheduling unchanged from R13 (best 92.6us): 2048 identical single-warp
//   CTA pair-tasks (L_p + L_{7-p} = 576 rows), single wave, no smem/syncs.

#define NUM_IN 8
#define BATCH 512
#define DVEC 32      // 128 floats = 32 float4 per row
#define BR 8         // rows per pipeline batch (L_i multiples of 64 -> N even)

struct Args {
    const float4* in[NUM_IN];
    int len[NUM_IN];
};

__device__ __forceinline__ void load_batch(float4* __restrict__ v,
                                           const float4* __restrict__ p) {
    #pragma unroll
    for (int u = 0; u < BR; ++u)
        v[u] = __ldcs(p + (size_t)u * DVEC);      // read-once: evict-first
}

__device__ __forceinline__ void sum_batch(float4& acc,
                                          const float4* __restrict__ v) {
    #pragma unroll
    for (int u = 0; u < BR; ++u) {
        acc.x += v[u].x; acc.y += v[u].y;
        acc.z += v[u].z; acc.w += v[u].w;
    }
}

// Sum L consecutive rows (L multiple of 64), lane's float4 column.
__device__ __forceinline__ float4 sum_rows_pipe(const float4* __restrict__ base,
                                                int L, int lane) {
    const float4* __restrict__ p = base + lane;
    float4 acc = make_float4(0.f, 0.f, 0.f, 0.f);

    float4 va[BR], vb[BR];
    load_batch(va, p);                            // batch 0 in flight
    p += BR * DVEC;

    // Consumes batches 1..N-2 (N/2 - 1 iterations); va holds batch N-2 after.
    for (int l = BR; l < L - BR; l += 2 * BR) {
        load_batch(vb, p);                        // issue batch k+1
        sum_batch(acc, va);                       // drain batch k
        p += BR * DVEC;
        load_batch(va, p);                        // issue batch k+2
        sum_batch(acc, vb);                       // drain batch k+1
        p += BR * DVEC;
    }

    load_batch(vb, p);                            // final batch N-1
    sum_batch(acc, va);                           // drain batch N-2
    sum_batch(acc, vb);                           // drain batch N-1
    return acc;
}

__global__ __launch_bounds__(32, 16)
void sum_cat_pair_pipe_kernel(Args args, float4* __restrict__ out) {
    const int lane = threadIdx.x;          // 32-thread CTA = one warp-task
    const int W    = blockIdx.x;           // task id in [0, 2048)

    const int p = W >> 9;                  // pair index 0..3
    const int b = W & (BATCH - 1);         // batch element

    const int iA = p;                      // shorter input of the pair
    const int iB = (NUM_IN - 1) - p;

    const int LA = args.len[iA];
    const int LB = args.len[iB];

    const float4* baseA = args.in[iA] + (size_t)b * (size_t)LA * DVEC;
    const float4* baseB = args.in[iB] + (size_t)b * (size_t)LB * DVEC;

    const float4 accA = sum_rows_pipe(baseA, LA, lane);
    const float4 accB = sum_rows_pipe(baseB, LB, lane);

    // out[b, i, :] -> float4 index (b*8 + i)*32 + lane
    out[((size_t)b * NUM_IN + iA) * DVEC + lane] = accA;
    out[((size_t)b * NUM_IN + iB) * DVEC + lane] = accB;
}

extern "C" void kernel_launch(void* const* d_in, const int* in_sizes, int n_in,
                              void* d_out, int out_size) {
    Args args;
    for (int i = 0; i < NUM_IN; ++i) {
        args.in[i]  = (const float4*)d_in[i];
        args.len[i] = in_sizes[i] / (BATCH * 128);   // = L_i
    }
    // 2048 identical single-warp CTA-tasks -> single wave, ~14 per SM.
    sum_cat_pair_pipe_kernel<<<(NUM_IN / 2) * BATCH, 32, 0, (cudaStream_t)0>>>(
        args, (float4*)d_out);
}

// round 17
// speedup vs baseline: 1.0441x; 1.0441x over previous
#include <cuda_runtime.h>

// Fused sum-over-seq + concat:  out[b,i,d] = sum_l x_i[b,l,d]
// 8 inputs x_i : [512, L_i, 128] fp32, L_i = 64*(i+1); out : [512, 8, 128] fp32.
//
// R17 = R16 pipeline + seam-bridged double buffering.
//   Task = (batch b, pair p): sum input p (LA rows) and input 7-p (LB rows),
//   LA + LB = 576. One 32-thread CTA per task -> 2048 identical CTAs,
//   single wave (~14/SM), no smem/syncs/atomics.
//   Stream loop: 8-row batches, double-buffered; B's first batch is issued
//   BEFORE A's last batch drains, so each warp always has >=8 LDG.128 in
//   flight across the entire 576-row task (R16 drained to 0 at the A->B seam).
//   Batch audit per segment (N = L/8, even): prologue b0; N/2-1 double-iters
//   consume b1..bN-2; epilogue loads bN-1. Exactly N batches, no OOB.

#define NUM_IN 8
#define BATCH 512
#define DVEC 32      // 128 floats = 32 float4 per row
#define BR 8         // rows per pipeline batch

struct Args {
    const float4* in[NUM_IN];
    int len[NUM_IN];
};

__device__ __forceinline__ void load_batch(float4* __restrict__ v,
                                           const float4* __restrict__ p) {
    #pragma unroll
    for (int u = 0; u < BR; ++u)
        v[u] = __ldcs(p + (size_t)u * DVEC);      // read-once: evict-first
}

__device__ __forceinline__ void sum_batch(float4& acc,
                                          const float4* __restrict__ v) {
    #pragma unroll
    for (int u = 0; u < BR; ++u) {
        acc.x += v[u].x; acc.y += v[u].y;
        acc.z += v[u].z; acc.w += v[u].w;
    }
}

__global__ __launch_bounds__(32, 16)
void sum_cat_pair_seam_kernel(Args args, float4* __restrict__ out) {
    const int lane = threadIdx.x;          // 32-thread CTA = one warp-task
    const int W    = blockIdx.x;           // task id in [0, 2048)

    const int p = W >> 9;                  // pair index 0..3
    const int b = W & (BATCH - 1);         // batch element

    const int iA = p;                      // shorter input of the pair
    const int iB = (NUM_IN - 1) - p;
    const int LA = args.len[iA];           // 64..256
    const int LB = args.len[iB];           // 320..512

    const float4* __restrict__ pA =
        args.in[iA] + (size_t)b * (size_t)LA * DVEC + lane;
    const float4* __restrict__ pB =
        args.in[iB] + (size_t)b * (size_t)LB * DVEC + lane;

    float4 accA = make_float4(0.f, 0.f, 0.f, 0.f);
    float4 accB = make_float4(0.f, 0.f, 0.f, 0.f);
    float4 va[BR], vb[BR];

    // ---- segment A ----
    load_batch(va, pA);                    // A batch 0 in flight
    pA += BR * DVEC;
    for (int l = BR; l < LA - BR; l += 2 * BR) {
        load_batch(vb, pA); sum_batch(accA, va); pA += BR * DVEC;
        load_batch(va, pA); sum_batch(accA, vb); pA += BR * DVEC;
    }
    load_batch(vb, pA);                    // A's final batch (N-1)
    sum_batch(accA, va);                   // drain A batch N-2
    // ---- seam: issue B batch 0 before draining A's last batch ----
    load_batch(va, pB);
    pB += BR * DVEC;
    sum_batch(accA, vb);                   // drain A batch N-1 (A complete)

    // ---- segment B (batch 0 already in va) ----
    for (int l = BR; l < LB - BR; l += 2 * BR) {
        load_batch(vb, pB); sum_batch(accB, va); pB += BR * DVEC;
        load_batch(va, pB); sum_batch(accB, vb); pB += BR * DVEC;
    }
    load_batch(vb, pB);                    // B's final batch
    sum_batch(accB, va);                   // drain B batch N-2
    sum_batch(accB, vb);                   // drain B batch N-1

    // out[b, i, :] -> float4 index (b*8 + i)*32 + lane
    out[((size_t)b * NUM_IN + iA) * DVEC + lane] = accA;
    out[((size_t)b * NUM_IN + iB) * DVEC + lane] = accB;
}

extern "C" void kernel_launch(void* const* d_in, const int* in_sizes, int n_in,
                              void* d_out, int out_size) {
    Args args;
    for (int i = 0; i < NUM_IN; ++i) {
        args.in[i]  = (const float4*)d_in[i];
        args.len[i] = in_sizes[i] / (BATCH * 128);   // = L_i
    }
    // 2048 identical single-warp CTA-tasks -> single wave, ~14 per SM.
    sum_cat_pair_seam_kernel<<<(NUM_IN / 2) * BATCH, 32, 0, (cudaStream_t)0>>>(
        args, (float4*)d_out);
}